// round 11
// baseline (speedup 1.0000x reference)
#include <cuda_runtime.h>

// Problem constants
#define NBC    6            // batch*channel = 2*3
#define NZ     128
#define NY     128
#define NX     128
#define VOL    (NZ*NY*NX)   // 2097152 per (b,c) volume
#define ZSTR   (NY*NX)      // 16384
#define TY     8            // y-rows per block tile
#define ZCHUNK 16           // z-planes marched per block

#define ALPHA_F 0.001
#define MIU_F   1.0
#define EPS_F   1e-8f

// Scratch accumulators (no cudaMalloc allowed): [0]=region_in, [1]=region_out, [2]=curv
// Zero at module load; the last finishing block re-zeroes them after reading,
// so every graph replay starts clean (deterministic).
__device__ double   g_acc[3];
__device__ unsigned g_ticket;

__device__ __forceinline__ int clampi(int v, int lo, int hi) {
    return v < lo ? lo : (v > hi ? hi : v);
}

// grid = (NY/TY=16, NZ/ZCHUNK=8, NBC=6) = 768 blocks, blockDim (128,2) = 256 thr.
// All 768 blocks resident at once (5-6 per SM, 20.5KB smem each) -> no wave tail.
// Each block computes a (ZCHUNK z) x (TY y) x (128 x) tile, marching z with a
// 4-slot ring buffer of (TY+2) x 128 y_pred planes in shared memory.
__global__ __launch_bounds__(256)
void ace_main(const float* __restrict__ yp, const float* __restrict__ yt,
              float* __restrict__ out) {
    __shared__ float s[4][TY + 2][NX];   // 20.5 KB ring buffer
    __shared__ float red[3][8];

    const int bc = blockIdx.z;
    const int z0 = blockIdx.y * ZCHUNK;
    const int y0 = blockIdx.x * TY;

    const float* u = yp + (size_t)bc * VOL;
    const int tid = threadIdx.y * 128 + threadIdx.x;
    const int tx  = threadIdx.x;

    // ---- plane loader: (TY+2) x 128 with clamped y (z clamped by caller) ----
    auto load_plane = [&](int slot, int gz) {
        gz = clampi(gz, 0, NZ - 1);
        const float* __restrict__ src = u + gz * ZSTR;
        #pragma unroll
        for (int i = tid; i < (TY + 2) * NX; i += 256) {
            const int row = i >> 7;
            const int col = i & 127;
            const int gy  = clampi(y0 + row - 1, 0, NY - 1);
            s[slot][row][col] = src[gy * NX + col];
        }
    };

    // prologue: planes z0-1, z0, z0+1 into slots 3, 0, 1 (z0 multiple of 4)
    load_plane(3, z0 - 1);
    load_plane(0, z0);
    load_plane(1, z0 + 1);

    const int xm = tx > 0 ? tx - 1 : 0;
    const int xp = tx < NX - 1 ? tx + 1 : NX - 1;

    float acc_in = 0.f, acc_out = 0.f, acc_curv = 0.f;
    const float* __restrict__ ytb = yt + (size_t)bc * VOL + z0 * ZSTR + y0 * NX + tx;

    #pragma unroll 4
    for (int zz = 0; zz < ZCHUNK; zz++) {
        __syncthreads();
        // prefetch plane z+2 into the slot not read this iteration
        if (zz != ZCHUNK - 1) load_plane((zz + 2) & 3, z0 + zz + 2);

        const int sm_ = (zz + 3) & 3;   // z-1
        const int sc  =  zz      & 3;   // z
        const int sp  = (zz + 1) & 3;   // z+1

        #pragma unroll
        for (int ly = threadIdx.y; ly < TY; ly += 2) {
            const int sy = ly + 1;

            const float uc  = s[sc ][sy][tx];
            const float uzp = s[sp ][sy][tx];
            const float uzm = s[sm_][sy][tx];
            const float uyp = s[sc ][sy + 1][tx];
            const float uym = s[sc ][sy - 1][tx];
            const float uxp = s[sc ][sy][xp];
            const float uxm = s[sc ][sy][xm];

            // first derivatives (clamped-neighbor form == one-sided boundaries)
            const float ci = 0.5f * (uzp - uzm);
            const float cj = 0.5f * (uyp - uym);
            const float ck = 0.5f * (uxp - uxm);
            // second derivatives
            const float cii = uzp + uzm - 2.f * uc;
            const float cjj = uyp + uym - 2.f * uc;
            const float ckk = uxp + uxm - 2.f * uc;
            // mixed derivatives: m(c)[i] = c[clamp(i+1)] - c[clamp(i-1)]
            const float cij = 0.5f * ((s[sp ][sy + 1][tx] - s[sm_][sy + 1][tx])
                                    - (s[sp ][sy - 1][tx] - s[sm_][sy - 1][tx]));
            const float cik = 0.5f * ((s[sp ][sy][xp] - s[sm_][sy][xp])
                                    - (s[sp ][sy][xm] - s[sm_][sy][xm]));
            const float cjk = 0.5f * ((s[sc ][sy + 1][xp] - s[sc ][sy - 1][xp])
                                    - (s[sc ][sy + 1][xm] - s[sc ][sy - 1][xm]));

            const float ci2 = ci * ci, cj2 = cj * cj, ck2 = ck * ck;
            const float s2  = ci2 + cj2 + ck2;
            const float len = sqrtf(EPS_F + s2);
            const float curvature = (1.f + ci2 + cj2) * ckk
                                  + (1.f + cj2 + ck2) * cii
                                  + (1.f + ci2 + ck2) * cjj
                                  - 2.f * cik * cjk * cij;
            // curv^2*|len| with curv = |K|/(sqrt(1+s2)+EPS); (sqrt(1+s2)+EPS)^2 ~= 1+s2
            const float q = fabsf(curvature);
            acc_curv += __fdividef(q * q * len, 1.f + s2);

            // region term (y_true only at center voxel; coalesced global load)
            const float t = ytb[zz * ZSTR + ly * NX];
            const float tm1 = t - 1.f;
            acc_in  += uc * tm1 * tm1;
            acc_out += (1.f - uc) * t * t;
        }
    }

    // ---- block reduction: warp shuffle, then cross-warp via shared ----
    #pragma unroll
    for (int off = 16; off; off >>= 1) {
        acc_in   += __shfl_down_sync(0xffffffffu, acc_in,   off);
        acc_out  += __shfl_down_sync(0xffffffffu, acc_out,  off);
        acc_curv += __shfl_down_sync(0xffffffffu, acc_curv, off);
    }
    const int wid  = tid >> 5;
    const int lane = tid & 31;
    if (lane == 0) {
        red[0][wid] = acc_in;
        red[1][wid] = acc_out;
        red[2][wid] = acc_curv;
    }
    __syncthreads();
    if (tid == 0) {
        float a = 0.f, b = 0.f, c = 0.f;
        #pragma unroll
        for (int w = 0; w < 8; w++) {
            a += red[0][w];
            b += red[1][w];
            c += red[2][w];
        }
        atomicAdd(&g_acc[0], (double)a);
        atomicAdd(&g_acc[1], (double)b);
        atomicAdd(&g_acc[2], (double)c);

        // ---- last-block finalize (ticket wraps to 0 -> replay-deterministic) ----
        __threadfence();
        const unsigned total = gridDim.x * gridDim.y * gridDim.z;
        const unsigned t = atomicInc(&g_ticket, total - 1);
        if (t == total - 1) {
            const double region   = fabs(g_acc[0]) + fabs(g_acc[1]);   // MIU = 1
            const double elastica = (double)NBC * (double)VOL * ALPHA_F + g_acc[2];
            out[0] = (float)(region + elastica);
            g_acc[0] = 0.0; g_acc[1] = 0.0; g_acc[2] = 0.0;   // clean for next replay
            __threadfence();
        }
    }
}

extern "C" void kernel_launch(void* const* d_in, const int* in_sizes, int n_in,
                              void* d_out, int out_size) {
    const float* y_pred = (const float*)d_in[0];
    const float* y_true = (const float*)d_in[1];
    float* out = (float*)d_out;

    dim3 grid(NY / TY, NZ / ZCHUNK, NBC);   // (16, 8, 6) = 768 blocks
    dim3 block(128, 2);                     // 256 threads
    ace_main<<<grid, block>>>(y_pred, y_true, out);
}

// round 14
// speedup vs baseline: 2.1688x; 2.1688x over previous
#include <cuda_runtime.h>

// Problem constants
#define NBC  6            // batch*channel = 2*3
#define NZ   128
#define NY   128
#define NX   128
#define VOL  (NZ*NY*NX)   // 2097152 per (b,c) volume
#define ZC   8            // z-planes marched per block
#define TYB  8            // y-rows per block

#define ALPHA_F 0.001
#define EPS_F   1e-8f

// Scratch accumulators (module-load zeroed; last block re-zeroes after reading,
// so every graph replay starts clean -> deterministic).
__device__ double   g_acc[3];
__device__ unsigned g_ticket;

// blockDim = (32, 8): one warp spans the full x=128 row (4 floats/lane).
// grid = (NY/8=16, NZ/ZC=16, NBC=6) = 1536 blocks. No shared-memory tile, no
// barriers in the hot loop: 3 z-levels of center / dy / sy columns roll in
// registers; x-neighbors via in-quad selects + 6 warp shuffles per z-step.
__global__ __launch_bounds__(256, 3)
void ace_main(const float4* __restrict__ yp4, const float4* __restrict__ yt4,
              float* __restrict__ out) {
    const int lane = threadIdx.x;               // 0..31  -> x-quad [4*lane, 4*lane+4)
    const int ty   = threadIdx.y;               // 0..7
    const int y    = blockIdx.x * TYB + ty;     // 0..127
    const int z0   = blockIdx.y * ZC;
    const int bc   = blockIdx.z;

    const int yp_ = (y < NY - 1) ? y + 1 : NY - 1;
    const int ym_ = (y > 0)      ? y - 1 : 0;

    const float4* __restrict__ up = yp4 + (size_t)bc * (VOL / 4);
    const float4* __restrict__ ut = yt4 + (size_t)bc * (VOL / 4);

    // row index in float4 units
    auto ridx = [&](int zz, int yy) -> size_t {
        return ((size_t)zz * NY + yy) * 32 + lane;
    };

    // ---- prologue: fill rolled registers for z0-1, z0, z0+1 (clamped) ----
    const int zm1 = (z0 > 0) ? z0 - 1 : 0;
    float4 uc0 = up[ridx(zm1,    y)];
    float4 uc1 = up[ridx(z0,     y)];
    float4 uc2 = up[ridx(z0 + 1, y)];

    float4 p, m;
    p = up[ridx(zm1, yp_)];    m = up[ridx(zm1, ym_)];
    float4 dy0 = make_float4(p.x-m.x, p.y-m.y, p.z-m.z, p.w-m.w);
    p = up[ridx(z0, yp_)];     m = up[ridx(z0, ym_)];
    float4 dy1 = make_float4(p.x-m.x, p.y-m.y, p.z-m.z, p.w-m.w);
    float4 sy1 = make_float4(p.x+m.x, p.y+m.y, p.z+m.z, p.w+m.w);
    p = up[ridx(z0 + 1, yp_)]; m = up[ridx(z0 + 1, ym_)];
    float4 dy2 = make_float4(p.x-m.x, p.y-m.y, p.z-m.z, p.w-m.w);
    float4 sy2 = make_float4(p.x+m.x, p.y+m.y, p.z+m.z, p.w+m.w);

    float acc_in = 0.f, acc_out = 0.f, acc_curv = 0.f;

    #pragma unroll
    for (int zz = 0; zz < ZC; zz++) {
        const int z  = z0 + zz;
        const int zl = (z + 2 < NZ) ? z + 2 : NZ - 1;

        // prefetch z+2 (used next iteration -> full iteration of latency slack)
        const float4 t_c = up[ridx(zl, y)];
        const float4 t_p = up[ridx(zl, yp_)];
        const float4 t_m = up[ridx(zl, ym_)];
        const float4 t4  = ut[ridx(z, y)];

        // z-derivative helpers (vector)
        const float4 dzc = make_float4(uc2.x-uc0.x, uc2.y-uc0.y, uc2.z-uc0.z, uc2.w-uc0.w);
        const float4 szc = make_float4(uc2.x+uc0.x, uc2.y+uc0.y, uc2.z+uc0.z, uc2.w+uc0.w);

        // cross-lane x-halo (warp spans the whole row: shfl clamp == global clamp,
        // except lane edges where clamped neighbor is element 0 / 3 of own quad)
        float uc_l = __shfl_up_sync  (0xffffffffu, uc1.w, 1); if (lane == 0)  uc_l = uc1.x;
        float uc_r = __shfl_down_sync(0xffffffffu, uc1.x, 1); if (lane == 31) uc_r = uc1.w;
        float dz_l = __shfl_up_sync  (0xffffffffu, dzc.w, 1); if (lane == 0)  dz_l = dzc.x;
        float dz_r = __shfl_down_sync(0xffffffffu, dzc.x, 1); if (lane == 31) dz_r = dzc.w;
        float dy_l = __shfl_up_sync  (0xffffffffu, dy1.w, 1); if (lane == 0)  dy_l = dy1.x;
        float dy_r = __shfl_down_sync(0xffffffffu, dy1.x, 1); if (lane == 31) dy_r = dy1.w;

        // per-element stencil; xm/xp taken from the quad or the halo scalars
        auto voxel = [&](float uc, float dz, float sz, float dy, float sy,
                         float dY0, float dY2,
                         float cxm, float cxp, float dzxm, float dzxp,
                         float dyxm, float dyxp, float t) {
            const float ci  = 0.5f * dz;
            const float cj  = 0.5f * dy;
            const float ck  = 0.5f * (cxp - cxm);
            const float cii = sz - 2.f * uc;
            const float cjj = sy - 2.f * uc;
            const float ckk = cxp + cxm - 2.f * uc;
            const float cij = 0.5f * (dY2 - dY0);
            const float cik = 0.5f * (dzxp - dzxm);
            const float cjk = 0.5f * (dyxp - dyxm);

            const float ci2 = ci*ci, cj2 = cj*cj, ck2 = ck*ck;
            const float s2  = ci2 + cj2 + ck2;
            const float len = sqrtf(EPS_F + s2);
            const float K   = (1.f + ci2 + cj2) * ckk
                            + (1.f + cj2 + ck2) * cii
                            + (1.f + ci2 + ck2) * cjj
                            - 2.f * cik * cjk * cij;
            // curv^2 * |len|, with (sqrt(1+s2)+EPS)^2 ~= 1+s2  (rel err ~2e-8)
            const float q = fabsf(K);
            acc_curv += __fdividef(q * q * len, 1.f + s2);

            const float tm1 = t - 1.f;
            acc_in  += uc * tm1 * tm1;
            acc_out += (1.f - uc) * t * t;
        };

        voxel(uc1.x, dzc.x, szc.x, dy1.x, sy1.x, dy0.x, dy2.x,
              uc_l,  uc1.y, dz_l,  dzc.y, dy_l,  dy1.y, t4.x);
        voxel(uc1.y, dzc.y, szc.y, dy1.y, sy1.y, dy0.y, dy2.y,
              uc1.x, uc1.z, dzc.x, dzc.z, dy1.x, dy1.z, t4.y);
        voxel(uc1.z, dzc.z, szc.z, dy1.z, sy1.z, dy0.z, dy2.z,
              uc1.y, uc1.w, dzc.y, dzc.w, dy1.y, dy1.w, t4.z);
        voxel(uc1.w, dzc.w, szc.w, dy1.w, sy1.w, dy0.w, dy2.w,
              uc1.z, uc_r,  dzc.z, dz_r,  dy1.z, dy_r,  t4.w);

        // roll the z-window
        uc0 = uc1; uc1 = uc2; uc2 = t_c;
        dy0 = dy1; dy1 = dy2;
        dy2 = make_float4(t_p.x-t_m.x, t_p.y-t_m.y, t_p.z-t_m.z, t_p.w-t_m.w);
        sy1 = sy2;
        sy2 = make_float4(t_p.x+t_m.x, t_p.y+t_m.y, t_p.z+t_m.z, t_p.w+t_m.w);
    }

    // ---- reduction: warp shuffle -> smem -> 3 double atomics per block ----
    #pragma unroll
    for (int off = 16; off; off >>= 1) {
        acc_in   += __shfl_down_sync(0xffffffffu, acc_in,   off);
        acc_out  += __shfl_down_sync(0xffffffffu, acc_out,  off);
        acc_curv += __shfl_down_sync(0xffffffffu, acc_curv, off);
    }
    __shared__ float red[3][8];
    if (lane == 0) {
        red[0][ty] = acc_in;
        red[1][ty] = acc_out;
        red[2][ty] = acc_curv;
    }
    __syncthreads();
    if (lane == 0 && ty == 0) {
        float a = 0.f, b = 0.f, c = 0.f;
        #pragma unroll
        for (int w = 0; w < 8; w++) { a += red[0][w]; b += red[1][w]; c += red[2][w]; }
        atomicAdd(&g_acc[0], (double)a);
        atomicAdd(&g_acc[1], (double)b);
        atomicAdd(&g_acc[2], (double)c);

        __threadfence();
        const unsigned total = gridDim.x * gridDim.y * gridDim.z;
        const unsigned tk = atomicInc(&g_ticket, total - 1);   // wraps to 0 -> replay-safe
        if (tk == total - 1) {
            const double region   = fabs(g_acc[0]) + fabs(g_acc[1]);   // MIU = 1
            const double elastica = (double)NBC * (double)VOL * ALPHA_F + g_acc[2];
            out[0] = (float)(region + elastica);
            g_acc[0] = 0.0; g_acc[1] = 0.0; g_acc[2] = 0.0;
            __threadfence();
        }
    }
}

extern "C" void kernel_launch(void* const* d_in, const int* in_sizes, int n_in,
                              void* d_out, int out_size) {
    const float4* y_pred = (const float4*)d_in[0];
    const float4* y_true = (const float4*)d_in[1];
    float* out = (float*)d_out;

    dim3 grid(NY / TYB, NZ / ZC, NBC);   // (16, 16, 6) = 1536 blocks
    dim3 block(32, 8);                   // 256 threads, warp spans full x-row
    ace_main<<<grid, block>>>(y_pred, y_true, out);
}

// round 17
// speedup vs baseline: 2.7199x; 1.2541x over previous
#include <cuda_runtime.h>

// Problem constants
#define NBC  6            // batch*channel = 2*3
#define NZ   128
#define NY   128
#define NX   128
#define VOL  (NZ*NY*NX)   // 2097152 per (b,c) volume
#define ZC   8            // z-planes marched per block
#define TYB  8            // y-rows per block

#define ALPHA_F 0.001
#define EPS_F   1e-8f

// Scratch accumulators (module-load zeroed; last block re-zeroes after reading,
// so every graph replay starts clean -> deterministic). [0]=region, [1]=curv
__device__ double   g_acc[2];
__device__ unsigned g_ticket;

__device__ __forceinline__ float rsqrt_approx(float x) {
    float r;
    asm("rsqrt.approx.f32 %0, %1;" : "=f"(r) : "f"(x));
    return r;
}

// blockDim = (32, 8): one warp spans the full x=128 row (4 floats/lane).
// grid = (NY/8=16, NZ/ZC=16, NBC=6) = 1536 blocks. No shared-memory tile, no
// barriers in the hot loop: 3 z-levels of center / dy / sy columns roll in
// registers; x-neighbors via in-quad selects + 6 warp shuffles per z-step.
__global__ __launch_bounds__(256, 4)
void ace_main(const float4* __restrict__ yp4, const float4* __restrict__ yt4,
              float* __restrict__ out) {
    const int lane = threadIdx.x;               // 0..31  -> x-quad [4*lane, 4*lane+4)
    const int ty   = threadIdx.y;               // 0..7
    const int y    = blockIdx.x * TYB + ty;     // 0..127
    const int z0   = blockIdx.y * ZC;
    const int bc   = blockIdx.z;

    const int yp_ = (y < NY - 1) ? y + 1 : NY - 1;
    const int ym_ = (y > 0)      ? y - 1 : 0;

    const float4* __restrict__ up = yp4 + (size_t)bc * (VOL / 4);
    const float4* __restrict__ ut = yt4 + (size_t)bc * (VOL / 4);

    // row index in float4 units
    auto ridx = [&](int zz, int yy) -> size_t {
        return ((size_t)zz * NY + yy) * 32 + lane;
    };

    // ---- prologue: fill rolled registers for z0-1, z0, z0+1 (clamped) ----
    const int zm1 = (z0 > 0) ? z0 - 1 : 0;
    float4 uc0 = up[ridx(zm1,    y)];
    float4 uc1 = up[ridx(z0,     y)];
    float4 uc2 = up[ridx(z0 + 1, y)];

    float4 p, m;
    p = up[ridx(zm1, yp_)];    m = up[ridx(zm1, ym_)];
    float4 dy0 = make_float4(p.x-m.x, p.y-m.y, p.z-m.z, p.w-m.w);
    p = up[ridx(z0, yp_)];     m = up[ridx(z0, ym_)];
    float4 dy1 = make_float4(p.x-m.x, p.y-m.y, p.z-m.z, p.w-m.w);
    float4 sy1 = make_float4(p.x+m.x, p.y+m.y, p.z+m.z, p.w+m.w);
    p = up[ridx(z0 + 1, yp_)]; m = up[ridx(z0 + 1, ym_)];
    float4 dy2 = make_float4(p.x-m.x, p.y-m.y, p.z-m.z, p.w-m.w);
    float4 sy2 = make_float4(p.x+m.x, p.y+m.y, p.z+m.z, p.w+m.w);

    float acc_reg = 0.f, acc_curv = 0.f;

    #pragma unroll
    for (int zz = 0; zz < ZC; zz++) {
        const int z  = z0 + zz;
        const int zl = (z + 2 < NZ) ? z + 2 : NZ - 1;

        // prefetch z+2 (used next iteration -> full iteration of latency slack)
        const float4 t_c = up[ridx(zl, y)];
        const float4 t_p = up[ridx(zl, yp_)];
        const float4 t_m = up[ridx(zl, ym_)];
        const float4 t4  = ut[ridx(z, y)];

        // z-derivative helpers (vector)
        const float4 dzc = make_float4(uc2.x-uc0.x, uc2.y-uc0.y, uc2.z-uc0.z, uc2.w-uc0.w);
        const float4 szc = make_float4(uc2.x+uc0.x, uc2.y+uc0.y, uc2.z+uc0.z, uc2.w+uc0.w);

        // cross-lane x-halo (warp spans the whole row: shfl clamp == global clamp,
        // except lane edges where clamped neighbor is element 0 / 3 of own quad)
        float uc_l = __shfl_up_sync  (0xffffffffu, uc1.w, 1); if (lane == 0)  uc_l = uc1.x;
        float uc_r = __shfl_down_sync(0xffffffffu, uc1.x, 1); if (lane == 31) uc_r = uc1.w;
        float dz_l = __shfl_up_sync  (0xffffffffu, dzc.w, 1); if (lane == 0)  dz_l = dzc.x;
        float dz_r = __shfl_down_sync(0xffffffffu, dzc.x, 1); if (lane == 31) dz_r = dzc.w;
        float dy_l = __shfl_up_sync  (0xffffffffu, dy1.w, 1); if (lane == 0)  dy_l = dy1.x;
        float dy_r = __shfl_down_sync(0xffffffffu, dy1.x, 1); if (lane == 31) dy_r = dy1.w;

        // per-element stencil; xm/xp taken from the quad or the halo scalars
        auto voxel = [&](float uc, float dz, float sz, float dy, float sy,
                         float dY0, float dY2,
                         float cxm, float cxp, float dzxm, float dzxp,
                         float dyxm, float dyxp, float t) {
            const float ci  = 0.5f * dz;
            const float cj  = 0.5f * dy;
            const float ck  = 0.5f * (cxp - cxm);
            const float cii = sz - 2.f * uc;
            const float cjj = sy - 2.f * uc;
            const float ckk = cxp + cxm - 2.f * uc;
            const float cij = 0.5f * (dY2 - dY0);
            const float cik = 0.5f * (dzxp - dzxm);
            const float cjk = 0.5f * (dyxp - dyxm);

            const float ci2 = ci*ci, cj2 = cj*cj, ck2 = ck*ck;
            const float s2  = ci2 + cj2 + ck2;
            const float lap = cii + cjj + ckk;
            const float K   = lap
                            + ci2 * (cjj + ckk)
                            + cj2 * (cii + ckk)
                            + ck2 * (cii + cjj)
                            - 2.f * cik * cjk * cij;
            // summand = K^2 * sqrt(EPS+s2) / (sqrt(1+s2)+EPS)^2
            //        ~= K^2 * a * rsqrt(a*b*b)   with a=EPS+s2, b=1+s2  (1 MUFU)
            const float a = EPS_F + s2;
            const float b = 1.f + s2;
            acc_curv += K * K * a * rsqrt_approx(a * b * b);

            // region: uc*(t-1)^2 + (1-uc)*t^2 = uc + t*(t - 2*uc); per-voxel
            // nonneg (inputs in [0,1]) so |sum_in|+|sum_out| == sum of this.
            acc_reg += fmaf(t, t - 2.f * uc, uc);
        };

        voxel(uc1.x, dzc.x, szc.x, dy1.x, sy1.x, dy0.x, dy2.x,
              uc_l,  uc1.y, dz_l,  dzc.y, dy_l,  dy1.y, t4.x);
        voxel(uc1.y, dzc.y, szc.y, dy1.y, sy1.y, dy0.y, dy2.y,
              uc1.x, uc1.z, dzc.x, dzc.z, dy1.x, dy1.z, t4.y);
        voxel(uc1.z, dzc.z, szc.z, dy1.z, sy1.z, dy0.z, dy2.z,
              uc1.y, uc1.w, dzc.y, dzc.w, dy1.y, dy1.w, t4.z);
        voxel(uc1.w, dzc.w, szc.w, dy1.w, sy1.w, dy0.w, dy2.w,
              uc1.z, uc_r,  dzc.z, dz_r,  dy1.z, dy_r,  t4.w);

        // roll the z-window
        uc0 = uc1; uc1 = uc2; uc2 = t_c;
        dy0 = dy1; dy1 = dy2;
        dy2 = make_float4(t_p.x-t_m.x, t_p.y-t_m.y, t_p.z-t_m.z, t_p.w-t_m.w);
        sy1 = sy2;
        sy2 = make_float4(t_p.x+t_m.x, t_p.y+t_m.y, t_p.z+t_m.z, t_p.w+t_m.w);
    }

    // ---- reduction: warp shuffle -> smem -> 2 double atomics per block ----
    #pragma unroll
    for (int off = 16; off; off >>= 1) {
        acc_reg  += __shfl_down_sync(0xffffffffu, acc_reg,  off);
        acc_curv += __shfl_down_sync(0xffffffffu, acc_curv, off);
    }
    __shared__ float red[2][8];
    if (lane == 0) {
        red[0][ty] = acc_reg;
        red[1][ty] = acc_curv;
    }
    __syncthreads();
    if (lane == 0 && ty == 0) {
        float a = 0.f, c = 0.f;
        #pragma unroll
        for (int w = 0; w < 8; w++) { a += red[0][w]; c += red[1][w]; }
        atomicAdd(&g_acc[0], (double)a);
        atomicAdd(&g_acc[1], (double)c);

        __threadfence();
        const unsigned total = gridDim.x * gridDim.y * gridDim.z;
        const unsigned tk = atomicInc(&g_ticket, total - 1);   // wraps to 0 -> replay-safe
        if (tk == total - 1) {
            const double region   = fabs(g_acc[0]);            // MIU = 1
            const double elastica = (double)NBC * (double)VOL * ALPHA_F + g_acc[1];
            out[0] = (float)(region + elastica);
            g_acc[0] = 0.0; g_acc[1] = 0.0;
            __threadfence();
        }
    }
}

extern "C" void kernel_launch(void* const* d_in, const int* in_sizes, int n_in,
                              void* d_out, int out_size) {
    const float4* y_pred = (const float4*)d_in[0];
    const float4* y_true = (const float4*)d_in[1];
    float* out = (float*)d_out;

    dim3 grid(NY / TYB, NZ / ZC, NBC);   // (16, 16, 6) = 1536 blocks
    dim3 block(32, 8);                   // 256 threads, warp spans full x-row
    ace_main<<<grid, block>>>(y_pred, y_true, out);
}